// round 12
// baseline (speedup 1.0000x reference)
#include <cuda_runtime.h>
#include <cstdint>

// GATv2 2-layer forward.
// x[2,1024,128], adj[2,1024,1024] i32, W1[64,128], a1[8], W2[8,64], a2[8]
// out[2,1024,8] f32
//
// Score identity: leaky(s) = 0.6*s + 0.4*|s|; softmax is invariant to the
// per-i constant, so:
//   log2e*e'(i,j,h) = C[j,h] + sum_f (0.4*log2e*a_f)*|g_i,f + g_j,f|
// with C = 0.6*log2e*(a . g) computed in the GEMM epilogues.
// Max-free softmax (scores O(1); partials sum linearly).
// 4 launches: [adj2bits||gemm1+C] -> attn1 -> gemm2+C -> attn2.

#define LOG2E 1.4426950408889634f
typedef unsigned long long u64;
typedef unsigned int u32;

__device__ __forceinline__ float fexp2(float x) {
    float y;
    asm("ex2.approx.ftz.f32 %0, %1;" : "=f"(y) : "f"(x));
    return y;
}
__device__ __forceinline__ u64 add2(u64 a, u64 b) {
    u64 o; asm("add.rn.f32x2 %0,%1,%2;" : "=l"(o) : "l"(a), "l"(b)); return o;
}
__device__ __forceinline__ u64 mul2(u64 a, u64 b) {
    u64 o; asm("mul.rn.f32x2 %0,%1,%2;" : "=l"(o) : "l"(a), "l"(b)); return o;
}
__device__ __forceinline__ u64 fma2(u64 a, u64 b, u64 c) {
    u64 o; asm("fma.rn.f32x2 %0,%1,%2,%3;" : "=l"(o) : "l"(a), "l"(b), "l"(c)); return o;
}
__device__ __forceinline__ u64 pack2(float lo, float hi) {
    u64 o; asm("mov.b64 %0,{%1,%2};" : "=l"(o) : "f"(lo), "f"(hi)); return o;
}
__device__ __forceinline__ float2 unpack2(u64 a) {
    float2 r; asm("mov.b64 {%0,%1},%2;" : "=f"(r.x), "=f"(r.y) : "l"(a)); return r;
}

// scratch (allocation-free rule: __device__ globals)
__device__ float d_g1[2 * 1024 * 64];
__device__ float d_h1[2 * 1024 * 64];
__device__ float d_g2[2 * 1024 * 8];
__device__ float d_c1[2 * 1024 * 8];
__device__ float d_c2[2 * 1024];
__device__ unsigned d_bits[2 * 1024 * 32];

// ---------------------------------------------------------------------------
// Fused pre-pass. Blocks [0,1024): adjacency->bitmask. Blocks [1024,1536):
// gemm1 out[M,64] = X[M,128] @ W[64,128]^T with fused C epilogue.
// Dot product kept in 4 partial chains (dep depth 32, not 128).
// ---------------------------------------------------------------------------
__global__ __launch_bounds__(256) void fused_pre(
    const int* __restrict__ adj, unsigned* __restrict__ bits,
    const float* __restrict__ X, const float* __restrict__ W,
    const float* __restrict__ A, float* __restrict__ g1,
    float* __restrict__ C) {
    constexpr int D = 128, K = 64, RPB = 4;
    __shared__ float wsh[D * (K + 1)];
    int tid = threadIdx.x;

    if (blockIdx.x < 1024) {  // ---- adj2bits ----
        int gw = (blockIdx.x * 256 + tid) >> 5;
        int lane = tid & 31;
        int v[8];
        size_t base = (size_t)gw * 8 * 32 + lane;
#pragma unroll
        for (int k = 0; k < 8; k++) v[k] = adj[base + k * 32];
#pragma unroll
        for (int k = 0; k < 8; k++) {
            unsigned m = __ballot_sync(0xffffffffu, v[k] != 0);
            if (lane == 0) bits[gw * 8 + k] = m;
        }
        return;
    }
    // ---- gemm1 + C ----
    int bid = blockIdx.x - 1024;
    for (int idx = tid; idx < D * K; idx += 256) {
        int c = idx / D, d = idx % D;
        wsh[d * (K + 1) + c] = W[idx];
    }
    __syncthreads();
    int c = tid % K;
    int r = bid * RPB + tid / K;
    const float4* x4 = (const float4*)(X + (size_t)r * D);
    float a0 = 0.f, a1v = 0.f, a2v = 0.f, a3 = 0.f;
#pragma unroll
    for (int d4 = 0; d4 < D / 4; d4++) {
        float4 xv = __ldg(x4 + d4);
        a0 = fmaf(xv.x, wsh[(d4 * 4 + 0) * (K + 1) + c], a0);
        a1v = fmaf(xv.y, wsh[(d4 * 4 + 1) * (K + 1) + c], a1v);
        a2v = fmaf(xv.z, wsh[(d4 * 4 + 2) * (K + 1) + c], a2v);
        a3 = fmaf(xv.w, wsh[(d4 * 4 + 3) * (K + 1) + c], a3);
    }
    float acc = (a0 + a1v) + (a2v + a3);
    g1[(size_t)r * K + c] = acc;
    float t = acc * __ldg(A + (c & 7));
    t += __shfl_xor_sync(0xffffffffu, t, 1);
    t += __shfl_xor_sync(0xffffffffu, t, 2);
    t += __shfl_xor_sync(0xffffffffu, t, 4);
    if ((c & 7) == 0) C[(size_t)r * (K / 8) + (c >> 3)] = 0.6f * LOG2E * t;
}

// ---------------------------------------------------------------------------
// gemm2: warp-per-row. out[M,8] = X[M,64] @ W[8,64]^T, fused C epilogue.
// ---------------------------------------------------------------------------
__global__ __launch_bounds__(256) void gemm2_kernel(
    const float* __restrict__ X, const float* __restrict__ W,
    const float* __restrict__ A, float* __restrict__ out,
    float* __restrict__ C, int M) {
    __shared__ float wsh[8 * 64];
    int tid = threadIdx.x;
    for (int i = tid; i < 512; i += 256) wsh[i] = W[i];
    __syncthreads();
    int w = tid >> 5, lane = tid & 31;
    int r = blockIdx.x * 8 + w;
    float2 x = *(const float2*)(X + (size_t)r * 64 + lane * 2);
    float p[8];
#pragma unroll
    for (int k = 0; k < 8; k++) {
        float2 wv = *(const float2*)&wsh[k * 64 + lane * 2];
        p[k] = x.x * wv.x + x.y * wv.y;
    }
#pragma unroll
    for (int off = 16; off >= 1; off >>= 1) {
#pragma unroll
        for (int k = 0; k < 8; k++) p[k] += __shfl_xor_sync(0xffffffffu, p[k], off);
    }
    if (lane == 0) {
        float cacc = 0.f;
#pragma unroll
        for (int k = 0; k < 8; k++) {
            out[(size_t)r * 8 + k] = p[k];
            cacc = fmaf(p[k], __ldg(A + k), cacc);
        }
        C[r] = 0.6f * LOG2E * cacc;
    }
}

// ---------------------------------------------------------------------------
// attn layer 1: H=8, F=8. CTA = 512 thr = 16 warps = 4 rows x 4 j-splits
// (best-measured shape). TJ=128 tiles, 2 barriers/tile.
// lane = jg*8 + h. g tile stride 12/head (conflict-free LDS.128); C separate,
// stride 8 (conflict-free LDS.32). Staging q-permuted (conflict-free STS.128).
// ---------------------------------------------------------------------------
__global__ __launch_bounds__(512, 2) void attn1_kernel(
    const float* __restrict__ G, const unsigned* __restrict__ BITS,
    const float* __restrict__ C, const float* __restrict__ AW,
    float* __restrict__ OUT, int N) {
    constexpr int S = 96;
    constexpr int TJ = 128;

    extern __shared__ float smem[];
    float* gsh = smem;                 // TJ*S
    float* csh = smem + TJ * S;        // TJ*8
    float* psum = csh + TJ * 8;        // 16*8*9

    int tid = threadIdx.x;
    int w = tid >> 5, lane = tid & 31;
    int r = w & 3, sp = w >> 2;
    int h = lane & 7, jg = lane >> 3;
    int base = sp * 4 + jg;            // [0,16)

    int iflat = blockIdx.x * 4 + r;
    int b = iflat >> 10;

    const float* gp = G + (size_t)iflat * 64 + h * 8;
    float4 gi0 = *(const float4*)gp;
    float4 gi1 = *(const float4*)(gp + 4);
    u64 gp01 = pack2(gi0.x, gi0.y), gp23 = pack2(gi0.z, gi0.w);
    u64 gp45 = pack2(gi1.x, gi1.y), gp67 = pack2(gi1.z, gi1.w);

    u64 aw[4];
#pragma unroll
    for (int k = 0; k < 4; k++)
        aw[k] = pack2(0.4f * LOG2E * __ldg(AW + 2 * k),
                      0.4f * LOG2E * __ldg(AW + 2 * k + 1));
    const u64 amask = 0x7fffffff7fffffffULL;

    float l = 0.f;
    u64 a01 = 0, a23 = 0, a45 = 0, a67 = 0;

    const float4* gbase = (const float4*)(G + (size_t)b * N * 64);
    const float* cbase = C + (size_t)b * N * 8;
    const unsigned* bitsrow = BITS + (size_t)iflat * 32;
    const float* gl = gsh + base * S + h * 12;
    const float* cl = csh + base * 8 + h;

    for (int jt = 0; jt < N; jt += TJ) {
        __syncthreads();
        const float4* src = gbase + (size_t)jt * 16;
        for (int idx = tid; idx < TJ * 16; idx += 512) {
            int j = idx >> 4, qidx = idx & 15;
            int q = ((qidx & 7) << 1) | (qidx >> 3);
            *(float4*)&gsh[j * S + (q >> 1) * 12 + (q & 1) * 4] = src[(j << 4) | q];
        }
        const float* csrc = cbase + (size_t)jt * 8;
        for (int idx = tid; idx < TJ * 8; idx += 512) csh[idx] = csrc[idx];
        __syncthreads();

        uint4 bw = *(const uint4*)(bitsrow + (jt >> 5));
#pragma unroll
        for (int k = 0; k < 8; k++) {
            const float* gr = gl + k * (16 * S);
            ulonglong2 v0 = *(const ulonglong2*)gr;
            ulonglong2 v1 = *(const ulonglong2*)(gr + 4);
            float cj = cl[k * 128];
            unsigned wv = (k < 2) ? bw.x : (k < 4) ? bw.y : (k < 6) ? bw.z : bw.w;
            unsigned m = (wv >> (base + ((k & 1) << 4))) & 1u;

            u64 s01 = add2(gp01, v0.x), s23 = add2(gp23, v0.y);
            u64 s45 = add2(gp45, v1.x), s67 = add2(gp67, v1.y);
            u64 d = mul2(aw[0], s01 & amask);
            d = fma2(aw[1], s23 & amask, d);
            d = fma2(aw[2], s45 & amask, d);
            d = fma2(aw[3], s67 & amask, d);
            float2 ev = unpack2(d);
            float e = (ev.x + ev.y) + cj;
            float wgt = m ? fexp2(e) : 0.f;
            l += wgt;
            u64 wp = pack2(wgt, wgt);
            a01 = fma2(wp, v0.x, a01);
            a23 = fma2(wp, v0.y, a23);
            a45 = fma2(wp, v1.x, a45);
            a67 = fma2(wp, v1.y, a67);
        }
    }

    float2 f01 = unpack2(a01), f23 = unpack2(a23), f45 = unpack2(a45), f67 = unpack2(a67);
    float acc[8] = {f01.x, f01.y, f23.x, f23.y, f45.x, f45.y, f67.x, f67.y};
#pragma unroll
    for (int off = 8; off < 32; off <<= 1) {
        l += __shfl_xor_sync(0xffffffffu, l, off);
#pragma unroll
        for (int f = 0; f < 8; f++) acc[f] += __shfl_xor_sync(0xffffffffu, acc[f], off);
    }

    if (jg == 0) {
        float* p = psum + (w * 8 + h) * 9;
        p[0] = l;
#pragma unroll
        for (int f = 0; f < 8; f++) p[1 + f] = acc[f];
    }
    __syncthreads();
    if (sp == 0 && jg == 0) {
        float L = 0.f, A[8] = {0, 0, 0, 0, 0, 0, 0, 0};
#pragma unroll
        for (int ss = 0; ss < 4; ss++) {
            const float* p = psum + ((ss * 4 + r) * 8 + h) * 9;
            L += p[0];
#pragma unroll
            for (int f = 0; f < 8; f++) A[f] += p[1 + f];
        }
        float inv = 1.f / L;
        float o[8];
#pragma unroll
        for (int f = 0; f < 8; f++) {
            o[f] = A[f] * inv;
            o[f] = o[f] > 0.f ? o[f] : fexp2(o[f] * LOG2E) - 1.f;  // ELU
        }
        float* op = OUT + (size_t)iflat * 64 + h * 8;
        *(float4*)op = make_float4(o[0], o[1], o[2], o[3]);
        *(float4*)(op + 4) = make_float4(o[4], o[5], o[6], o[7]);
    }
}

// ---------------------------------------------------------------------------
// attn layer 2: H=1, F=8. NO shared memory: g2+C is 36KB/batch and L1-resident
// (228KB, zero smem carve-out), so each warp reads rows directly via __ldg.
// CTA = 128 thr = 4 warps = 4 rows, grid M/4 = 512. Lane L owns j = L + 32k,
// 32 fully-unrolled iterations (deep MLP); full-warp shfl reduce.
// ---------------------------------------------------------------------------
__global__ __launch_bounds__(128) void attn2_kernel(
    const float* __restrict__ G, const unsigned* __restrict__ BITS,
    const float* __restrict__ C, const float* __restrict__ AW,
    float* __restrict__ OUT, int N) {
    int tid = threadIdx.x;
    int w = tid >> 5, lane = tid & 31;
    int iflat = blockIdx.x * 4 + w;
    int b = iflat >> 10;

    const float* gp = G + (size_t)iflat * 8;
    float4 gi0 = *(const float4*)gp;
    float4 gi1 = *(const float4*)(gp + 4);
    u64 gp01 = pack2(gi0.x, gi0.y), gp23 = pack2(gi0.z, gi0.w);
    u64 gp45 = pack2(gi1.x, gi1.y), gp67 = pack2(gi1.z, gi1.w);

    u64 aw[4];
#pragma unroll
    for (int k = 0; k < 4; k++)
        aw[k] = pack2(0.4f * LOG2E * __ldg(AW + 2 * k),
                      0.4f * LOG2E * __ldg(AW + 2 * k + 1));
    const u64 amask = 0x7fffffff7fffffffULL;

    const ulonglong2* gb = (const ulonglong2*)(G + (size_t)b * N * 8);
    const float* cb = C + (size_t)b * N;
    const uint4* b4 = (const uint4*)(BITS + (size_t)iflat * 32);

    float l = 0.f;
    u64 a01 = 0, a23 = 0, a45 = 0, a67 = 0;

#pragma unroll
    for (int kk = 0; kk < 8; kk++) {
        uint4 bw = __ldg(b4 + kk);
#pragma unroll
        for (int k2 = 0; k2 < 4; k2++) {
            int j = lane + (kk * 4 + k2) * 32;
            ulonglong2 v = __ldg(gb + j);           // floats 0..3
            ulonglong2 v2 = __ldg(gb + j + (0));    // placeholder (row = 2x u64x2)
            // row j = 8 floats = 2 ulonglong2? No: 8 floats = 32B = one ulonglong2
            // covers 16B. Row needs two 16B loads:
            (void)v2;
            ulonglong2 vlo = __ldg((const ulonglong2*)(cb - cb) + 0);  // unused
            (void)vlo;
            const ulonglong2* rowp = (const ulonglong2*)((const char*)gb + (size_t)j * 32);
            ulonglong2 r0 = __ldg(rowp);        // floats 0..3 (two f32x2)
            ulonglong2 r1 = __ldg(rowp + 1);    // floats 4..7
            float cj = __ldg(cb + j);
            unsigned wv = (k2 == 0) ? bw.x : (k2 == 1) ? bw.y : (k2 == 2) ? bw.z : bw.w;
            unsigned m = (wv >> lane) & 1u;

            u64 s01 = add2(gp01, r0.x), s23 = add2(gp23, r0.y);
            u64 s45 = add2(gp45, r1.x), s67 = add2(gp67, r1.y);
            u64 d = mul2(aw[0], s01 & amask);
            d = fma2(aw[1], s23 & amask, d);
            d = fma2(aw[2], s45 & amask, d);
            d = fma2(aw[3], s67 & amask, d);
            float2 ev = unpack2(d);
            float e = (ev.x + ev.y) + cj;
            float wgt = m ? fexp2(e) : 0.f;
            l += wgt;
            u64 wp = pack2(wgt, wgt);
            a01 = fma2(wp, r0.x, a01);
            a23 = fma2(wp, r0.y, a23);
            a45 = fma2(wp, r1.x, a45);
            a67 = fma2(wp, r1.y, a67);
        }
    }

    float2 f01 = unpack2(a01), f23 = unpack2(a23), f45 = unpack2(a45), f67 = unpack2(a67);
    float acc[8] = {f01.x, f01.y, f23.x, f23.y, f45.x, f45.y, f67.x, f67.y};
#pragma unroll
    for (int off = 1; off < 32; off <<= 1) {
        l += __shfl_xor_sync(0xffffffffu, l, off);
#pragma unroll
        for (int f = 0; f < 8; f++) acc[f] += __shfl_xor_sync(0xffffffffu, acc[f], off);
    }

    if (lane == 0) {
        float inv = 1.f / l;
        float* op = OUT + (size_t)iflat * 8;
        *(float4*)op = make_float4(acc[0] * inv, acc[1] * inv, acc[2] * inv, acc[3] * inv);
        *(float4*)(op + 4) = make_float4(acc[4] * inv, acc[5] * inv, acc[6] * inv, acc[7] * inv);
    }
}

// ---------------------------------------------------------------------------

extern "C" void kernel_launch(void* const* d_in, const int* in_sizes, int n_in,
                              void* d_out, int out_size) {
    const float* x = (const float*)d_in[0];
    const int* adj = (const int*)d_in[1];
    const float* W1 = (const float*)d_in[2];
    const float* a1 = (const float*)d_in[3];
    const float* W2 = (const float*)d_in[4];
    const float* a2 = (const float*)d_in[5];
    float* out = (float*)d_out;

    const int B = 2, N = 1024, M = B * N;

    float *g1, *h1, *g2, *c1, *c2;
    unsigned* bits;
    cudaGetSymbolAddress((void**)&g1, d_g1);
    cudaGetSymbolAddress((void**)&h1, d_h1);
    cudaGetSymbolAddress((void**)&g2, d_g2);
    cudaGetSymbolAddress((void**)&c1, d_c1);
    cudaGetSymbolAddress((void**)&c2, d_c2);
    cudaGetSymbolAddress((void**)&bits, d_bits);

    const int SMEM1 = (128 * 96 + 128 * 8 + 16 * 8 * 9) * 4;  // 57856
    cudaFuncSetAttribute((const void*)attn1_kernel,
                         cudaFuncAttributeMaxDynamicSharedMemorySize, SMEM1);

    // K1: adj2bits (blocks 0..1023)  ||  gemm1+C (blocks 1024..1535)
    fused_pre<<<1536, 256>>>(adj, bits, x, W1, a1, g1, c1);
    // K2: attn1 (+ELU)
    attn1_kernel<<<M / 4, 512, SMEM1>>>(g1, bits, c1, a1, h1, N);
    // K3: gemm2+C (warp-per-row)
    gemm2_kernel<<<M / 8, 256>>>(h1, W2, a2, g2, c2, M);
    // K4: attn2 (no smem, L1-resident reads, warp-per-row)
    attn2_kernel<<<M / 4, 128>>>(g2, bits, c2, a2, out, N);
}

// round 13
// speedup vs baseline: 1.0949x; 1.0949x over previous
#include <cuda_runtime.h>
#include <cstdint>

// GATv2 2-layer forward.
// x[2,1024,128], adj[2,1024,1024] i32, W1[64,128], a1[8], W2[8,64], a2[8]
// out[2,1024,8] f32
//
// Score identity: leaky(s) = 0.6*s + 0.4*|s|; softmax is invariant to the
// per-i constant, so:
//   log2e*e'(i,j,h) = C[j,h] + sum_f (0.4*log2e*a_f)*|g_i,f + g_j,f|
// with C = 0.6*log2e*(a . g) computed in epilogues.
// Max-free softmax (scores O(1); partials sum linearly).
// 3 launches: [adj2bits||gemm1+C1] -> attn1(+ELU+gemm2+C2 fused) -> attn2.
// h1 never touches global memory: attn1's epilogue holds the full h1 row in
// registers and applies the row-local gemm2 (g2[r] = W2 @ h1[r]) directly.

#define LOG2E 1.4426950408889634f
typedef unsigned long long u64;
typedef unsigned int u32;

__device__ __forceinline__ float fexp2(float x) {
    float y;
    asm("ex2.approx.ftz.f32 %0, %1;" : "=f"(y) : "f"(x));
    return y;
}
__device__ __forceinline__ u64 add2(u64 a, u64 b) {
    u64 o; asm("add.rn.f32x2 %0,%1,%2;" : "=l"(o) : "l"(a), "l"(b)); return o;
}
__device__ __forceinline__ u64 mul2(u64 a, u64 b) {
    u64 o; asm("mul.rn.f32x2 %0,%1,%2;" : "=l"(o) : "l"(a), "l"(b)); return o;
}
__device__ __forceinline__ u64 fma2(u64 a, u64 b, u64 c) {
    u64 o; asm("fma.rn.f32x2 %0,%1,%2,%3;" : "=l"(o) : "l"(a), "l"(b), "l"(c)); return o;
}
__device__ __forceinline__ u64 pack2(float lo, float hi) {
    u64 o; asm("mov.b64 %0,{%1,%2};" : "=l"(o) : "f"(lo), "f"(hi)); return o;
}
__device__ __forceinline__ float2 unpack2(u64 a) {
    float2 r; asm("mov.b64 {%0,%1},%2;" : "=f"(r.x), "=f"(r.y) : "l"(a)); return r;
}

// scratch (allocation-free rule: __device__ globals)
__device__ float d_g1[2 * 1024 * 64];
__device__ float d_g2[2 * 1024 * 8];
__device__ float d_c1[2 * 1024 * 8];
__device__ float d_c2[2 * 1024];
__device__ unsigned d_bits[2 * 1024 * 32];

// ---------------------------------------------------------------------------
// Fused pre-pass. Blocks [0,1024): adjacency->bitmask. Blocks [1024,1536):
// gemm1 out[M,64] = X[M,128] @ W[64,128]^T with fused C1 epilogue.
// ---------------------------------------------------------------------------
__global__ __launch_bounds__(256) void fused_pre(
    const int* __restrict__ adj, unsigned* __restrict__ bits,
    const float* __restrict__ X, const float* __restrict__ W,
    const float* __restrict__ A, float* __restrict__ g1,
    float* __restrict__ C) {
    constexpr int D = 128, K = 64, RPB = 4;
    __shared__ float wsh[D * (K + 1)];
    int tid = threadIdx.x;

    if (blockIdx.x < 1024) {  // ---- adj2bits ----
        int gw = (blockIdx.x * 256 + tid) >> 5;
        int lane = tid & 31;
        int v[8];
        size_t base = (size_t)gw * 8 * 32 + lane;
#pragma unroll
        for (int k = 0; k < 8; k++) v[k] = adj[base + k * 32];
#pragma unroll
        for (int k = 0; k < 8; k++) {
            unsigned m = __ballot_sync(0xffffffffu, v[k] != 0);
            if (lane == 0) bits[gw * 8 + k] = m;
        }
        return;
    }
    // ---- gemm1 + C1 ----
    int bid = blockIdx.x - 1024;
    for (int idx = tid; idx < D * K; idx += 256) {
        int c = idx / D, d = idx % D;
        wsh[d * (K + 1) + c] = W[idx];
    }
    __syncthreads();
    int c = tid % K;
    int r = bid * RPB + tid / K;
    const float4* x4 = (const float4*)(X + (size_t)r * D);
    float a0 = 0.f, a1v = 0.f, a2v = 0.f, a3 = 0.f;
#pragma unroll
    for (int d4 = 0; d4 < D / 4; d4++) {
        float4 xv = __ldg(x4 + d4);
        a0 = fmaf(xv.x, wsh[(d4 * 4 + 0) * (K + 1) + c], a0);
        a1v = fmaf(xv.y, wsh[(d4 * 4 + 1) * (K + 1) + c], a1v);
        a2v = fmaf(xv.z, wsh[(d4 * 4 + 2) * (K + 1) + c], a2v);
        a3 = fmaf(xv.w, wsh[(d4 * 4 + 3) * (K + 1) + c], a3);
    }
    float acc = (a0 + a1v) + (a2v + a3);
    g1[(size_t)r * K + c] = acc;
    float t = acc * __ldg(A + (c & 7));
    t += __shfl_xor_sync(0xffffffffu, t, 1);
    t += __shfl_xor_sync(0xffffffffu, t, 2);
    t += __shfl_xor_sync(0xffffffffu, t, 4);
    if ((c & 7) == 0) C[(size_t)r * (K / 8) + (c >> 3)] = 0.6f * LOG2E * t;
}

// ---------------------------------------------------------------------------
// attn layer 1: H=8, F=8. CTA = 512 thr = 16 warps = 4 rows x 4 j-splits
// (best-measured shape). TJ=128 tiles, 2 barriers/tile.
// lane = jg*8 + h. g tile stride 12/head (conflict-free LDS.128); C separate,
// stride 8 (conflict-free LDS.32). Staging q-permuted (conflict-free STS.128).
// Epilogue: ELU then fused row-local gemm2 (g2[r] = W2 @ h1[r]) + C2.
// ---------------------------------------------------------------------------
__global__ __launch_bounds__(512, 2) void attn1_kernel(
    const float* __restrict__ G, const unsigned* __restrict__ BITS,
    const float* __restrict__ C, const float* __restrict__ AW,
    const float* __restrict__ W2, const float* __restrict__ A2,
    float* __restrict__ G2, float* __restrict__ C2, int N) {
    constexpr int S = 96;
    constexpr int TJ = 128;

    extern __shared__ float smem[];
    float* gsh = smem;                      // TJ*S
    float* csh = smem + TJ * S;             // TJ*8
    float* psum = csh + TJ * 8;             // 16*8*9
    float* w2sh = psum + 16 * 8 * 9;        // 8*64

    int tid = threadIdx.x;
    int w = tid >> 5, lane = tid & 31;
    int r = w & 3, sp = w >> 2;
    int h = lane & 7, jg = lane >> 3;
    int base = sp * 4 + jg;            // [0,16)

    int iflat = blockIdx.x * 4 + r;
    int b = iflat >> 10;

    // one-time W2 stage (visible after the first tile barrier)
    if (tid < 512) w2sh[tid] = W2[tid];

    const float* gp = G + (size_t)iflat * 64 + h * 8;
    float4 gi0 = *(const float4*)gp;
    float4 gi1 = *(const float4*)(gp + 4);
    u64 gp01 = pack2(gi0.x, gi0.y), gp23 = pack2(gi0.z, gi0.w);
    u64 gp45 = pack2(gi1.x, gi1.y), gp67 = pack2(gi1.z, gi1.w);

    u64 aw[4];
#pragma unroll
    for (int k = 0; k < 4; k++)
        aw[k] = pack2(0.4f * LOG2E * __ldg(AW + 2 * k),
                      0.4f * LOG2E * __ldg(AW + 2 * k + 1));
    const u64 amask = 0x7fffffff7fffffffULL;

    float l = 0.f;
    u64 a01 = 0, a23 = 0, a45 = 0, a67 = 0;

    const float4* gbase = (const float4*)(G + (size_t)b * N * 64);
    const float* cbase = C + (size_t)b * N * 8;
    const unsigned* bitsrow = BITS + (size_t)iflat * 32;
    const float* gl = gsh + base * S + h * 12;
    const float* cl = csh + base * 8 + h;

    for (int jt = 0; jt < N; jt += TJ) {
        __syncthreads();
        const float4* src = gbase + (size_t)jt * 16;
        for (int idx = tid; idx < TJ * 16; idx += 512) {
            int j = idx >> 4, qidx = idx & 15;
            int q = ((qidx & 7) << 1) | (qidx >> 3);
            *(float4*)&gsh[j * S + (q >> 1) * 12 + (q & 1) * 4] = src[(j << 4) | q];
        }
        const float* csrc = cbase + (size_t)jt * 8;
        for (int idx = tid; idx < TJ * 8; idx += 512) csh[idx] = csrc[idx];
        __syncthreads();

        uint4 bw = *(const uint4*)(bitsrow + (jt >> 5));
#pragma unroll
        for (int k = 0; k < 8; k++) {
            const float* gr = gl + k * (16 * S);
            ulonglong2 v0 = *(const ulonglong2*)gr;
            ulonglong2 v1 = *(const ulonglong2*)(gr + 4);
            float cj = cl[k * 128];
            unsigned wv = (k < 2) ? bw.x : (k < 4) ? bw.y : (k < 6) ? bw.z : bw.w;
            unsigned m = (wv >> (base + ((k & 1) << 4))) & 1u;

            u64 s01 = add2(gp01, v0.x), s23 = add2(gp23, v0.y);
            u64 s45 = add2(gp45, v1.x), s67 = add2(gp67, v1.y);
            u64 d = mul2(aw[0], s01 & amask);
            d = fma2(aw[1], s23 & amask, d);
            d = fma2(aw[2], s45 & amask, d);
            d = fma2(aw[3], s67 & amask, d);
            float2 ev = unpack2(d);
            float e = (ev.x + ev.y) + cj;
            float wgt = m ? fexp2(e) : 0.f;
            l += wgt;
            u64 wp = pack2(wgt, wgt);
            a01 = fma2(wp, v0.x, a01);
            a23 = fma2(wp, v0.y, a23);
            a45 = fma2(wp, v1.x, a45);
            a67 = fma2(wp, v1.y, a67);
        }
    }

    float2 f01 = unpack2(a01), f23 = unpack2(a23), f45 = unpack2(a45), f67 = unpack2(a67);
    float acc[8] = {f01.x, f01.y, f23.x, f23.y, f45.x, f45.y, f67.x, f67.y};
#pragma unroll
    for (int off = 8; off < 32; off <<= 1) {
        l += __shfl_xor_sync(0xffffffffu, l, off);
#pragma unroll
        for (int f = 0; f < 8; f++) acc[f] += __shfl_xor_sync(0xffffffffu, acc[f], off);
    }

    if (jg == 0) {
        float* p = psum + (w * 8 + h) * 9;
        p[0] = l;
#pragma unroll
        for (int f = 0; f < 8; f++) p[1 + f] = acc[f];
    }
    __syncthreads();
    if (sp == 0 && jg == 0) {   // warps 0..3 (w == r), lanes 0..7 (lane == h)
        float L = 0.f, A[8] = {0, 0, 0, 0, 0, 0, 0, 0};
#pragma unroll
        for (int ss = 0; ss < 4; ss++) {
            const float* p = psum + ((ss * 4 + r) * 8 + h) * 9;
            L += p[0];
#pragma unroll
            for (int f = 0; f < 8; f++) A[f] += p[1 + f];
        }
        float inv = 1.f / L;
        float o[8];
#pragma unroll
        for (int f = 0; f < 8; f++) {
            o[f] = A[f] * inv;
            o[f] = o[f] > 0.f ? o[f] : fexp2(o[f] * LOG2E) - 1.f;  // ELU
        }
        // fused gemm2: pk[k] = sum_f W2[k, h*8+f] * o[f]; reduce over 8 h-lanes
        float pk[8];
#pragma unroll
        for (int k = 0; k < 8; k++) {
            const float* wrow = w2sh + k * 64 + h * 8;
            float s = wrow[0] * o[0];
            s = fmaf(wrow[1], o[1], s);
            s = fmaf(wrow[2], o[2], s);
            s = fmaf(wrow[3], o[3], s);
            s = fmaf(wrow[4], o[4], s);
            s = fmaf(wrow[5], o[5], s);
            s = fmaf(wrow[6], o[6], s);
            s = fmaf(wrow[7], o[7], s);
            pk[k] = s;
        }
#pragma unroll
        for (int off = 1; off < 8; off <<= 1) {
#pragma unroll
            for (int k = 0; k < 8; k++)
                pk[k] += __shfl_xor_sync(0x000000ffu, pk[k], off);
        }
        if (h == 0) {
            float* op = G2 + (size_t)iflat * 8;
            *(float4*)op = make_float4(pk[0], pk[1], pk[2], pk[3]);
            *(float4*)(op + 4) = make_float4(pk[4], pk[5], pk[6], pk[7]);
            float cacc = 0.f;
#pragma unroll
            for (int k = 0; k < 8; k++) cacc = fmaf(pk[k], __ldg(A2 + k), cacc);
            C2[iflat] = 0.6f * LOG2E * cacc;
        }
    }
}

// ---------------------------------------------------------------------------
// attn layer 2: H=1, F=8. CTA = 256 thr = 8 warps = 8 rows (best-measured
// R10 form). Whole g2 batch staged once; C separate stride-1. Lane L owns
// j = L + 32k; 32 fully-unrolled iterations; full-warp shfl reduce.
// ---------------------------------------------------------------------------
__global__ __launch_bounds__(256) void attn2_kernel(
    const float* __restrict__ G, const unsigned* __restrict__ BITS,
    const float* __restrict__ C, const float* __restrict__ AW,
    float* __restrict__ OUT, int N) {
    extern __shared__ float smem[];
    float* gsh = smem;            // N*12
    float* csh = smem + N * 12;   // N

    int tid = threadIdx.x;
    int w = tid >> 5, lane = tid & 31;
    int iflat = blockIdx.x * 8 + w;
    int b = iflat >> 10;

    const float4* gb = (const float4*)(G + (size_t)b * N * 8);
    const float* cb = C + (size_t)b * N;
    {
        int jb = tid & 127, q = tid >> 7;  // phase: same q, consecutive j
#pragma unroll
        for (int it = 0; it < 8; it++) {
            int j = jb + it * 128;
            *(float4*)&gsh[j * 12 + q * 4] = gb[j * 2 + q];
        }
    }
    for (int idx = tid; idx < N; idx += 256) csh[idx] = cb[idx];
    __syncthreads();

    const float* gp = G + (size_t)iflat * 8;
    float4 gi0 = *(const float4*)gp;
    float4 gi1 = *(const float4*)(gp + 4);
    u64 gp01 = pack2(gi0.x, gi0.y), gp23 = pack2(gi0.z, gi0.w);
    u64 gp45 = pack2(gi1.x, gi1.y), gp67 = pack2(gi1.z, gi1.w);

    u64 aw[4];
#pragma unroll
    for (int k = 0; k < 4; k++)
        aw[k] = pack2(0.4f * LOG2E * __ldg(AW + 2 * k),
                      0.4f * LOG2E * __ldg(AW + 2 * k + 1));
    const u64 amask = 0x7fffffff7fffffffULL;

    const uint4* b4 = (const uint4*)(BITS + (size_t)iflat * 32);
    const float* gl = gsh + lane * 12;
    const float* cl = csh + lane;

    float l = 0.f;
    u64 a01 = 0, a23 = 0, a45 = 0, a67 = 0;

#pragma unroll
    for (int kk = 0; kk < 8; kk++) {
        uint4 bw = b4[kk];
#pragma unroll
        for (int k2 = 0; k2 < 4; k2++) {
            const float* gr = gl + (kk * 4 + k2) * (32 * 12);
            ulonglong2 v0 = *(const ulonglong2*)gr;
            ulonglong2 v1 = *(const ulonglong2*)(gr + 4);
            float cj = cl[(kk * 4 + k2) * 32];
            unsigned wv = (k2 == 0) ? bw.x : (k2 == 1) ? bw.y : (k2 == 2) ? bw.z : bw.w;
            unsigned m = (wv >> lane) & 1u;

            u64 s01 = add2(gp01, v0.x), s23 = add2(gp23, v0.y);
            u64 s45 = add2(gp45, v1.x), s67 = add2(gp67, v1.y);
            u64 d = mul2(aw[0], s01 & amask);
            d = fma2(aw[1], s23 & amask, d);
            d = fma2(aw[2], s45 & amask, d);
            d = fma2(aw[3], s67 & amask, d);
            float2 ev = unpack2(d);
            float e = (ev.x + ev.y) + cj;
            float wgt = m ? fexp2(e) : 0.f;
            l += wgt;
            u64 wp = pack2(wgt, wgt);
            a01 = fma2(wp, v0.x, a01);
            a23 = fma2(wp, v0.y, a23);
            a45 = fma2(wp, v1.x, a45);
            a67 = fma2(wp, v1.y, a67);
        }
    }

    float2 f01 = unpack2(a01), f23 = unpack2(a23), f45 = unpack2(a45), f67 = unpack2(a67);
    float acc[8] = {f01.x, f01.y, f23.x, f23.y, f45.x, f45.y, f67.x, f67.y};
#pragma unroll
    for (int off = 1; off < 32; off <<= 1) {
        l += __shfl_xor_sync(0xffffffffu, l, off);
#pragma unroll
        for (int f = 0; f < 8; f++) acc[f] += __shfl_xor_sync(0xffffffffu, acc[f], off);
    }

    if (lane == 0) {
        float inv = 1.f / l;
        float* op = OUT + (size_t)iflat * 8;
        *(float4*)op = make_float4(acc[0] * inv, acc[1] * inv, acc[2] * inv, acc[3] * inv);
        *(float4*)(op + 4) = make_float4(acc[4] * inv, acc[5] * inv, acc[6] * inv, acc[7] * inv);
    }
}

// ---------------------------------------------------------------------------

extern "C" void kernel_launch(void* const* d_in, const int* in_sizes, int n_in,
                              void* d_out, int out_size) {
    const float* x = (const float*)d_in[0];
    const int* adj = (const int*)d_in[1];
    const float* W1 = (const float*)d_in[2];
    const float* a1 = (const float*)d_in[3];
    const float* W2 = (const float*)d_in[4];
    const float* a2 = (const float*)d_in[5];
    float* out = (float*)d_out;

    const int B = 2, N = 1024, M = B * N;

    float *g1, *g2, *c1, *c2;
    unsigned* bits;
    cudaGetSymbolAddress((void**)&g1, d_g1);
    cudaGetSymbolAddress((void**)&g2, d_g2);
    cudaGetSymbolAddress((void**)&c1, d_c1);
    cudaGetSymbolAddress((void**)&c2, d_c2);
    cudaGetSymbolAddress((void**)&bits, d_bits);

    const int SMEM1 = (128 * 96 + 128 * 8 + 16 * 8 * 9 + 512) * 4;  // 59904
    const int SMEM2 = (N * 12 + N) * 4;                              // 53248
    cudaFuncSetAttribute((const void*)attn1_kernel,
                         cudaFuncAttributeMaxDynamicSharedMemorySize, SMEM1);
    cudaFuncSetAttribute((const void*)attn2_kernel,
                         cudaFuncAttributeMaxDynamicSharedMemorySize, SMEM2);

    // K1: adj2bits (blocks 0..1023)  ||  gemm1+C1 (blocks 1024..1535)
    fused_pre<<<1536, 256>>>(adj, bits, x, W1, a1, g1, c1);
    // K2: attn1 (+ELU +gemm2 +C2 fused)
    attn1_kernel<<<M / 4, 512, SMEM1>>>(g1, bits, c1, a1, W2, a2, g2, c2, N);
    // K3: attn2
    attn2_kernel<<<M / 8, 256, SMEM2>>>(g2, bits, c2, a2, out, N);
}